// round 15
// baseline (speedup 1.0000x reference)
#include <cuda_runtime.h>
#include <cuda_fp16.h>
#include <cstdint>

// ---------------- scratch (device globals; no allocation allowed) ----------------
__device__ float    g_y1[4*32*64*64];    // cv1 output
__device__ float    g_y [4*64*64*64];    // cv2 output
__device__ uint32_t g_q [4*4096*4];      // q[b][n][8] f16x2-packed, pre-scaled by log2(e)
__device__ uint32_t g_k [4*4096*4];      // k[b][n][8] f16x2-packed
__device__ uint32_t g_vt[4*64*2048];     // v^T [b][ch][n/2] f16x2-packed

__device__ __forceinline__ float silu_f(float t) {
    return t * (1.0f / (1.0f + __expf(-t)));
}
__device__ __forceinline__ uint32_t f2h2(float lo, float hi) {
    uint32_t r;
    asm("cvt.rn.f16x2.f32 %0, %1, %2;" : "=r"(r) : "f"(hi), "f"(lo));
    return r;
}
__device__ __forceinline__ uint16_t h16b(float v) {
    uint16_t r;
    asm("cvt.rn.f16.f32 %0, %1;" : "=h"(r) : "f"(v));
    return r;
}
__device__ __forceinline__ uint32_t ex2h2(uint32_t x) {
    uint32_t r;
    asm("ex2.approx.f16x2 %0, %1;" : "=r"(r) : "r"(x));
    return r;
}
__device__ __forceinline__ uint32_t smem_u32(const void* p) {
    uint32_t a;
    asm("{ .reg .u64 t; cvta.to.shared.u64 t, %1; cvt.u32.u64 %0, t; }" : "=r"(a) : "l"(p));
    return a;
}
__device__ __forceinline__ float to_tf32(float x) {
    uint32_t r;
    asm("cvt.rna.tf32.f32 %0, %1;" : "=r"(r) : "f"(x));
    return __uint_as_float(r);
}
__device__ __forceinline__ void mma_tf32(float c[4], uint32_t a0, uint32_t a1,
                                         uint32_t a2, uint32_t a3,
                                         uint32_t b0, uint32_t b1) {
    asm volatile(
        "mma.sync.aligned.m16n8k8.row.col.f32.tf32.tf32.f32 "
        "{%0,%1,%2,%3}, {%4,%5,%6,%7}, {%8,%9}, {%0,%1,%2,%3};"
        : "+f"(c[0]), "+f"(c[1]), "+f"(c[2]), "+f"(c[3])
        : "r"(a0), "r"(a1), "r"(a2), "r"(a3), "r"(b0), "r"(b1));
}
__device__ __forceinline__ void cp16(uint32_t smem_dst, const void* gsrc) {
    asm volatile("cp.async.cg.shared.global [%0], [%1], 16;"
                 :: "r"(smem_dst), "l"(gsrc) : "memory");
}

// ======== conv1: 3x3+BN+SiLU tf32 TC, 8x8 tile, grid 256 (R11 exact) ========
__global__ void __launch_bounds__(256, 2) conv1_kernel(
        const float* __restrict__ xin, const float* __restrict__ w,
        const float* __restrict__ bg, const float* __restrict__ bb,
        const float* __restrict__ bm, const float* __restrict__ bv,
        float* __restrict__ out) {
    constexpr int WSTR = 32*9 + 8;   // 296
    extern __shared__ __align__(16) float sm[];
    float* x_s = sm;                 // 3840 floats
    float* w_s = sm + 3840;          // 32*296 floats

    const int b   = blockIdx.z;
    const int gy0 = blockIdx.y * 8;
    const int gx0 = blockIdx.x * 8;
    const int tid = threadIdx.x;
    const int wid = tid >> 5, lane = tid & 31;
    const int ct = wid & 1, nq = wid >> 1;
    const int lg = lane >> 2, lt = lane & 3;
    const int co0 = ct*16;

    float C[2][4];
#pragma unroll
    for (int i = 0; i < 2; i++)
#pragma unroll
        for (int j = 0; j < 4; j++) C[i][j] = 0.f;

    for (int ch = 0; ch < 2; ch++) {
        const float* xb = xin + (size_t)(b*64 + ch*32)*4096;
        for (int e = tid; e < 3200; e += 256) {
            int ci = e / 100, rem = e % 100;
            int r = rem / 10, c = rem % 10;
            int gy = gy0 - 1 + r, gx = gx0 - 1 + c;
            float val = 0.f;
            if ((unsigned)gy < 64u && (unsigned)gx < 64u)
                val = xb[ci*4096 + gy*64 + gx];
            x_s[(ci*10 + r)*12 + c] = to_tf32(val);
        }
        for (int e = tid; e < 9216; e += 256) {
            int co = e / 288, rem = e % 288;
            int ci = rem / 9, tap = rem % 9;
            w_s[ci*WSTR + co*9 + tap] = to_tf32(w[(co*64 + ch*32 + ci)*9 + tap]);
        }
        __syncthreads();

#pragma unroll
        for (int cc = 0; cc < 4; cc++) {
            const int ci0 = cc*8;
            uint32_t a[9][4];
#pragma unroll
            for (int tap = 0; tap < 9; tap++) {
                a[tap][0] = __float_as_uint(w_s[(ci0 + lt)*WSTR + (co0 + lg)*9 + tap]);
                a[tap][1] = __float_as_uint(w_s[(ci0 + lt)*WSTR + (co0 + 8 + lg)*9 + tap]);
                a[tap][2] = __float_as_uint(w_s[(ci0 + 4 + lt)*WSTR + (co0 + lg)*9 + tap]);
                a[tap][3] = __float_as_uint(w_s[(ci0 + 4 + lt)*WSTR + (co0 + 8 + lg)*9 + tap]);
            }
#pragma unroll
            for (int nt = 0; nt < 2; nt++) {
                const int py = nq*2 + nt;
#pragma unroll
                for (int tap = 0; tap < 9; tap++) {
                    const int dy = tap / 3, dx = tap % 3;
                    const int colb = (py + dy)*12 + dx + lg;
                    uint32_t b0 = __float_as_uint(x_s[(ci0 + lt)*120 + colb]);
                    uint32_t b1 = __float_as_uint(x_s[(ci0 + 4 + lt)*120 + colb]);
                    mma_tf32(C[nt], a[tap][0], a[tap][1], a[tap][2], a[tap][3], b0, b1);
                }
            }
        }
        __syncthreads();
    }

#pragma unroll
    for (int nt = 0; nt < 2; nt++) {
        const int py = nq*2 + nt;
#pragma unroll
        for (int h = 0; h < 2; h++) {
            int co = co0 + h*8 + lg;
            float scale = bg[co] * rsqrtf(bv[co] + 1e-5f);
            float shift = bb[co] - bm[co]*scale;
            float2 v;
            v.x = silu_f(C[nt][2*h]  *scale + shift);
            v.y = silu_f(C[nt][2*h+1]*scale + shift);
            *reinterpret_cast<float2*>(out + (((size_t)(b*32 + co)*64 + gy0 + py)*64 + gx0 + 2*lt)) = v;
        }
    }
}

// ======== conv2 (tf32 TC, 16x8 tile, grid 128) + fused QKV (f16 out, v^T) ========
__global__ void __launch_bounds__(256) conv2_qkv_kernel(
        const float* __restrict__ xin, const float* __restrict__ w,
        const float* __restrict__ bg, const float* __restrict__ bb,
        const float* __restrict__ bm, const float* __restrict__ bv,
        const float* __restrict__ q_w, const float* __restrict__ q_b,
        const float* __restrict__ k_w, const float* __restrict__ k_b,
        const float* __restrict__ v_w, const float* __restrict__ v_b,
        float* __restrict__ out,
        uint32_t* __restrict__ gqo, uint32_t* __restrict__ gko,
        uint32_t* __restrict__ gvt) {
    constexpr int COUT = 64;
    constexpr float LOG2E = 1.4426950408889634f;
    extern __shared__ __align__(16) float sm[];
    float* x_s = sm;                // [32][10][20]
    float* w_s = sm + 6400;         // [ci 32][co 64][12]
    // phase-2 overlay:
    float* y_t  = sm;               // [128][65] = 8320 floats
    float* wq_s = sm + 8320;        // [64][80]
    float* qb_s = sm + 8320 + 5120; // [80]
    uint16_t* v_sm = reinterpret_cast<uint16_t*>(sm + 13520);  // [64ch][128px] f16 (16KB)

    const int b   = blockIdx.z;
    const int gy0 = blockIdx.y * 8;
    const int gx0 = blockIdx.x * 16;
    const int tid = threadIdx.x;
    const int wid = tid >> 5, lane = tid & 31;
    const int ct = wid & 3, nh = wid >> 2;
    const int lg = lane >> 2, lt = lane & 3;

    float C[8][4];
#pragma unroll
    for (int i = 0; i < 8; i++)
#pragma unroll
        for (int j = 0; j < 4; j++) C[i][j] = 0.f;

    {
        const float* xb = xin + (size_t)(b*32)*4096;
        for (int e = tid; e < 32*10*18; e += 256) {
            int ci = e / 180; int rem = e % 180;
            int r = rem / 18, c = rem % 18;
            int gy = gy0 - 1 + r, gx = gx0 - 1 + c;
            float val = 0.f;
            if ((unsigned)gy < 64u && (unsigned)gx < 64u)
                val = xb[ci*4096 + gy*64 + gx];
            x_s[(ci*10 + r)*20 + c] = to_tf32(val);
        }
        for (int e = tid; e < 64*32*9; e += 256) {
            int co = e / 288, rem = e % 288;
            int ci = rem / 9, tap = rem % 9;
            w_s[(ci*64 + co)*12 + tap] = to_tf32(w[e]);
        }
        __syncthreads();

#pragma unroll
        for (int cc = 0; cc < 4; cc++) {
            const int ci0 = cc*8;
            uint32_t a[9][4];
            const int co0 = ct*16;
#pragma unroll
            for (int tap = 0; tap < 9; tap++) {
                a[tap][0] = __float_as_uint(w_s[((ci0 + lt)*64 + co0 + lg)*12 + tap]);
                a[tap][1] = __float_as_uint(w_s[((ci0 + lt)*64 + co0 + 8 + lg)*12 + tap]);
                a[tap][2] = __float_as_uint(w_s[((ci0 + 4 + lt)*64 + co0 + lg)*12 + tap]);
                a[tap][3] = __float_as_uint(w_s[((ci0 + 4 + lt)*64 + co0 + 8 + lg)*12 + tap]);
            }
#pragma unroll
            for (int nt = 0; nt < 8; nt++) {
                const int n0 = (nh*8 + nt)*8;
                const int py = n0 >> 4, px0 = n0 & 15;
#pragma unroll
                for (int tap = 0; tap < 9; tap++) {
                    const int dy = tap / 3, dx = tap % 3;
                    const int colb = (py + dy)*20 + px0 + dx + lg;
                    uint32_t b0 = __float_as_uint(x_s[(ci0 + lt)*200 + colb]);
                    uint32_t b1 = __float_as_uint(x_s[(ci0 + 4 + lt)*200 + colb]);
                    mma_tf32(C[nt], a[tap][0], a[tap][1], a[tap][2], a[tap][3], b0, b1);
                }
            }
        }
        __syncthreads();
    }

    // epilogue: BN + SiLU -> gmem y AND smem y_t[px][co]
#pragma unroll
    for (int nt = 0; nt < 8; nt++) {
        const int n0 = (nh*8 + nt)*8;
        const int py = n0 >> 4;
        const int px = (n0 & 15) + 2*lt;
#pragma unroll
        for (int h = 0; h < 2; h++) {
            int co = ct*16 + h*8 + lg;
            float scale = bg[co] * rsqrtf(bv[co] + 1e-5f);
            float shift = bb[co] - bm[co]*scale;
            float v0 = silu_f(C[nt][2*h]  *scale + shift);
            float v1 = silu_f(C[nt][2*h+1]*scale + shift);
            *reinterpret_cast<float2*>(out + (((size_t)(b*COUT + co)*64 + gy0 + py)*64 + gx0 + px)) =
                make_float2(v0, v1);
            y_t[(py*16 + px)*65 + co]     = v0;
            y_t[(py*16 + px + 1)*65 + co] = v1;
        }
    }
    // qkv weights ([64][80] c-major) + biases
    for (int e = tid; e < 5120; e += 256) {
        int c = e / 80, o = e % 80;
        float val;
        if (o < 8)       val = q_w[o*64 + c];
        else if (o < 16) val = k_w[(o-8)*64 + c];
        else             val = v_w[(o-16)*64 + c];
        wq_s[c*80 + o] = val;
    }
    if (tid < 80) {
        float val;
        if (tid < 8)       val = q_b[tid];
        else if (tid < 16) val = k_b[tid-8];
        else               val = v_b[tid-16];
        qb_s[tid] = val;
    }
    __syncthreads();

    // qkv: 2 threads per pixel, 40 outputs each
    const int px   = tid >> 1;
    const int half = tid & 1;
    float a2[40];
    const float* bb2 = qb_s + half*40;
#pragma unroll
    for (int j = 0; j < 40; j++) a2[j] = bb2[j];
    for (int c = 0; c < 64; c++) {
        float yv = y_t[px*65 + c];
        const float4* wp = reinterpret_cast<const float4*>(wq_s + c*80 + half*40);
#pragma unroll
        for (int j4 = 0; j4 < 10; j4++) {
            float4 w4 = wp[j4];
            a2[j4*4+0] = fmaf(w4.x, yv, a2[j4*4+0]);
            a2[j4*4+1] = fmaf(w4.y, yv, a2[j4*4+1]);
            a2[j4*4+2] = fmaf(w4.z, yv, a2[j4*4+2]);
            a2[j4*4+3] = fmaf(w4.w, yv, a2[j4*4+3]);
        }
    }
    const int n = (gy0 + (px >> 4))*64 + gx0 + (px & 15);
    const size_t row = (size_t)(b*4096 + n);
    if (half == 0) {
        // q scaled by log2(e) so flash can use ex2 directly; f16 packed
        *reinterpret_cast<uint4*>(gqo + row*4) = make_uint4(
            f2h2(a2[0]*LOG2E, a2[1]*LOG2E), f2h2(a2[2]*LOG2E, a2[3]*LOG2E),
            f2h2(a2[4]*LOG2E, a2[5]*LOG2E), f2h2(a2[6]*LOG2E, a2[7]*LOG2E));
        *reinterpret_cast<uint4*>(gko + row*4) = make_uint4(
            f2h2(a2[8],  a2[9]),  f2h2(a2[10], a2[11]),
            f2h2(a2[12], a2[13]), f2h2(a2[14], a2[15]));
#pragma unroll
        for (int j = 0; j < 24; j++)
            v_sm[j*128 + px] = h16b(a2[16 + j]);
    } else {
#pragma unroll
        for (int j = 0; j < 40; j++)
            v_sm[(24 + j)*128 + px] = h16b(a2[j]);
    }
    __syncthreads();

    // coalesced v^T write: g_vt[b][ch][n/2]
    const uint32_t* v32 = reinterpret_cast<const uint32_t*>(v_sm);
    for (int i = tid; i < 4096; i += 256) {
        int chn = i >> 6, lp = i & 63;
        int np = (gy0 + (lp >> 3))*32 + (gx0 >> 1) + (lp & 7);
        gvt[((size_t)(b*64 + chn))*2048 + np] = v32[chn*64 + lp];
    }
}

// ---------------- flash attention: f16 mma + ex2.approx.f16x2 softmax ----------------
__global__ void __launch_bounds__(256, 1) flash_hmma_kernel(
        const uint32_t* __restrict__ gq,
        const uint32_t* __restrict__ gk,
        const uint32_t* __restrict__ gvt,
        const float* __restrict__ x,
        const float* __restrict__ gy,
        const float* __restrict__ gamma,
        float* __restrict__ outp) {
    extern __shared__ __align__(128) unsigned char smem_all[];
    const uint32_t smb = smem_u32(smem_all);
    float* t_s = reinterpret_cast<float*>(smem_all);   // epilogue overlay [128][66]

    const int b    = blockIdx.y;
    const int qt   = blockIdx.x;
    const int tid  = threadIdx.x;
    const int wid  = tid >> 5;
    const int lane = tid & 31;
    const int g    = lane >> 2;
    const int t    = lane & 3;

    const int qrow = b*4096 + qt*128 + wid*16 + g;
    const uint32_t qa0 = gq[(size_t)qrow*4 + t];
    const uint32_t qa1 = gq[(size_t)(qrow+8)*4 + t];

    float o[8][4];
#pragma unroll
    for (int i = 0; i < 8; i++)
#pragma unroll
        for (int j = 0; j < 4; j++) o[i][j] = 0.f;
    float rs0 = 0.f, rs1 = 0.f;

    const uint32_t* kb = gk + (size_t)b*4096*4;
    const uint32_t* vtb = gvt + (size_t)b*64*2048;

    const int sel  = lane >> 3;
    const int l8   = lane & 7;
    const int ch_off    = ((sel >> 1) << 3) + l8;
    const int chunk_off = sel & 1;

    auto issue_tile = [&](int kt, int buf) {
        if (tid < 128)
            cp16(smb + (uint32_t)(buf*2048) + tid*16,
                 kb + (size_t)(kt*128 + tid)*4);
        uint32_t vbase = smb + 6144u + (uint32_t)buf*17408u;
#pragma unroll
        for (int it = 0; it < 4; it++) {
            int c = it*256 + tid;
            int ch = c >> 4, chunk = c & 15;
            cp16(vbase + (uint32_t)(ch*272 + (((chunk ^ (ch>>3)) & 15) << 4)),
                 vtb + (size_t)ch*2048 + kt*64 + chunk*4);
        }
        asm volatile("cp.async.commit_group;" ::: "memory");
    };

    issue_tile(0, 0);
    issue_tile(1, 1);

    for (int kt = 0; kt < 32; kt++) {
        const int cur = kt % 3;
        if (kt < 31) {
            asm volatile("cp.async.wait_group 1;" ::: "memory");
        } else {
            asm volatile("cp.async.wait_group 0;" ::: "memory");
        }
        __syncthreads();
        if (kt + 2 < 32)
            issue_tile(kt + 2, (kt + 2) % 3);

        const unsigned char* Kc = smem_all + cur*2048;
        const uint32_t vbase = smb + 6144u + (uint32_t)cur*17408u;

        // ---- QK (f16) + ex2 softmax; e2[nt][0/1] are PV A-operand halves ----
        uint32_t e2[16][2];
#pragma unroll
        for (int nt = 0; nt < 16; nt++) {
            uint32_t kb32 = *reinterpret_cast<const uint32_t*>(Kc + nt*128 + lane*4);
            float d0 = 0.f, d1 = 0.f, d2 = 0.f, d3 = 0.f;
            asm volatile(
                "mma.sync.aligned.m16n8k8.row.col.f32.f16.f16.f32 "
                "{%0,%1,%2,%3}, {%4,%5}, {%6}, {%0,%1,%2,%3};"
                : "+f"(d0), "+f"(d1), "+f"(d2), "+f"(d3)
                : "r"(qa0), "r"(qa1), "r"(kb32));
            uint32_t plo = ex2h2(f2h2(d0, d1));
            uint32_t phi = ex2h2(f2h2(d2, d3));
            e2[nt][0] = plo;
            e2[nt][1] = phi;
            float2 flo = __half22float2(*reinterpret_cast<__half2*>(&plo));
            float2 fhi = __half22float2(*reinterpret_cast<__half2*>(&phi));
            rs0 += flo.x + flo.y;
            rs1 += fhi.x + fhi.y;
        }

        // ---- PV (f16) ----
#pragma unroll
        for (int ks = 0; ks < 8; ks++) {
            uint32_t a0 = e2[2*ks][0],   a1 = e2[2*ks][1];
            uint32_t a2 = e2[2*ks+1][0], a3 = e2[2*ks+1][1];
            int chunk = 2*ks + chunk_off;
#pragma unroll
            for (int nt2 = 0; nt2 < 4; nt2++) {
                int ch = nt2*16 + ch_off;
                uint32_t addr = vbase + (uint32_t)(ch*272 + (((chunk ^ (ch>>3)) & 15) << 4));
                uint32_t b0, b1, b2, b3;
                asm volatile(
                    "ldmatrix.sync.aligned.m8n8.x4.shared.b16 {%0,%1,%2,%3}, [%4];"
                    : "=r"(b0), "=r"(b1), "=r"(b2), "=r"(b3) : "r"(addr));
                asm volatile(
                    "mma.sync.aligned.m16n8k16.row.col.f32.f16.f16.f32 "
                    "{%0,%1,%2,%3}, {%4,%5,%6,%7}, {%8,%9}, {%0,%1,%2,%3};"
                    : "+f"(o[nt2*2][0]), "+f"(o[nt2*2][1]), "+f"(o[nt2*2][2]), "+f"(o[nt2*2][3])
                    : "r"(a0), "r"(a1), "r"(a2), "r"(a3), "r"(b0), "r"(b1));
                asm volatile(
                    "mma.sync.aligned.m16n8k16.row.col.f32.f16.f16.f32 "
                    "{%0,%1,%2,%3}, {%4,%5,%6,%7}, {%8,%9}, {%0,%1,%2,%3};"
                    : "+f"(o[nt2*2+1][0]), "+f"(o[nt2*2+1][1]), "+f"(o[nt2*2+1][2]), "+f"(o[nt2*2+1][3])
                    : "r"(a0), "r"(a1), "r"(a2), "r"(a3), "r"(b2), "r"(b3));
            }
        }
        __syncthreads();
    }

    // ---- normalize + transpose via smem + fused epilogue ----
    rs0 += __shfl_xor_sync(0xffffffffu, rs0, 1);
    rs0 += __shfl_xor_sync(0xffffffffu, rs0, 2);
    rs1 += __shfl_xor_sync(0xffffffffu, rs1, 1);
    rs1 += __shfl_xor_sync(0xffffffffu, rs1, 2);
    const float inv0 = 1.0f / rs0, inv1 = 1.0f / rs1;

    const int r0 = wid*16 + g;
#pragma unroll
    for (int nt = 0; nt < 8; nt++) {
        int ch = nt*8 + 2*t;
        *reinterpret_cast<float2*>(t_s + r0*66 + ch) =
            make_float2(o[nt][0]*inv0, o[nt][1]*inv0);
        *reinterpret_cast<float2*>(t_s + (r0+8)*66 + ch) =
            make_float2(o[nt][2]*inv1, o[nt][3]*inv1);
    }
    __syncthreads();

    const float g2 = 2.0f * gamma[0];
    const int c  = tid >> 2;
    const int i0 = (tid & 3) * 32;
    const size_t base = ((size_t)(b*64 + c))*4096 + qt*128 + i0;
#pragma unroll
    for (int i4 = 0; i4 < 8; i4++) {
        float4 xv = *reinterpret_cast<const float4*>(x  + base + i4*4);
        float4 yv = *reinterpret_cast<const float4*>(gy + base + i4*4);
        float4 ov;
        ov.x = xv.x + 2.f*yv.x + g2*t_s[(i0 + i4*4 + 0)*66 + c];
        ov.y = xv.y + 2.f*yv.y + g2*t_s[(i0 + i4*4 + 1)*66 + c];
        ov.z = xv.z + 2.f*yv.z + g2*t_s[(i0 + i4*4 + 2)*66 + c];
        ov.w = xv.w + 2.f*yv.w + g2*t_s[(i0 + i4*4 + 3)*66 + c];
        *reinterpret_cast<float4*>(outp + base + i4*4) = ov;
    }
}

// ---------------- launch ----------------
extern "C" void kernel_launch(void* const* d_in, const int* in_sizes, int n_in,
                              void* d_out, int out_size) {
    const float* x     = (const float*)d_in[0];
    const float* cv1_w = (const float*)d_in[1];
    const float* bn1_g = (const float*)d_in[2];
    const float* bn1_b = (const float*)d_in[3];
    const float* bn1_m = (const float*)d_in[4];
    const float* bn1_v = (const float*)d_in[5];
    const float* cv2_w = (const float*)d_in[6];
    const float* bn2_g = (const float*)d_in[7];
    const float* bn2_b = (const float*)d_in[8];
    const float* bn2_m = (const float*)d_in[9];
    const float* bn2_v = (const float*)d_in[10];
    const float* q_w   = (const float*)d_in[11];
    const float* q_b   = (const float*)d_in[12];
    const float* k_w   = (const float*)d_in[13];
    const float* k_b   = (const float*)d_in[14];
    const float* v_w   = (const float*)d_in[15];
    const float* v_b   = (const float*)d_in[16];
    const float* gamma = (const float*)d_in[17];
    float* out = (float*)d_out;

    void *py1, *py, *pq, *pk, *pvt;
    cudaGetSymbolAddress(&py1, g_y1);
    cudaGetSymbolAddress(&py,  g_y);
    cudaGetSymbolAddress(&pq,  g_q);
    cudaGetSymbolAddress(&pk,  g_k);
    cudaGetSymbolAddress(&pvt, g_vt);

    const int SMEM_C1 = (3840 + 32*296) * 4;     // 53248
    const int SMEM_C2 = (6400 + 32*64*12) * 4;   // 123904
    const int SMEM_FL = 3*2048 + 3*17408;        // 58368

    cudaFuncSetAttribute(conv1_kernel, cudaFuncAttributeMaxDynamicSharedMemorySize, SMEM_C1);
    cudaFuncSetAttribute(conv2_qkv_kernel, cudaFuncAttributeMaxDynamicSharedMemorySize, SMEM_C2);
    cudaFuncSetAttribute(flash_hmma_kernel, cudaFuncAttributeMaxDynamicSharedMemorySize, SMEM_FL);

    conv1_kernel<<<dim3(8,8,4), 256, SMEM_C1>>>(
        x, cv1_w, bn1_g, bn1_b, bn1_m, bn1_v, (float*)py1);
    conv2_qkv_kernel<<<dim3(4,8,4), 256, SMEM_C2>>>(
        (const float*)py1, cv2_w, bn2_g, bn2_b, bn2_m, bn2_v,
        q_w, q_b, k_w, k_b, v_w, v_b,
        (float*)py, (uint32_t*)pq, (uint32_t*)pk, (uint32_t*)pvt);
    flash_hmma_kernel<<<dim3(32,4), 256, SMEM_FL>>>(
        (const uint32_t*)pq, (const uint32_t*)pk, (const uint32_t*)pvt,
        x, (const float*)py, gamma, out);
}

// round 16
// speedup vs baseline: 1.0876x; 1.0876x over previous
#include <cuda_runtime.h>
#include <cstdint>

// ---------------- scratch (device globals; no allocation allowed) ----------------
__device__ float    g_y1[4*32*64*64];    // cv1 output
__device__ float    g_y [4*64*64*64];    // cv2 output
__device__ uint32_t g_q [4*4096*4];      // q[b][n][8] bf16x2-packed
__device__ uint32_t g_k [4*4096*4];      // k[b][n][8] bf16x2-packed
__device__ uint32_t g_vt[4*64*2048];     // v^T [b][ch][n/2] bf16x2-packed
// prepped weights (smem-image layouts, BN-scale folded, tf32-rounded)
__device__ float    g_w1tf[2*32*296];    // conv1: [ch][ci*296 + co*9 + tap]
__device__ float    g_w2tf[32*64*12];    // conv2: [(ci*64+co)*12 + tap]
__device__ float    g_wq  [64*80];       // qkv:  [c*80 + o]
__device__ float    g_sh1[32];
__device__ float    g_sh2[64];
__device__ float    g_qb [80];

__device__ __forceinline__ float silu_f(float t) {
    return t * (1.0f / (1.0f + __expf(-t)));
}
__device__ __forceinline__ uint32_t f2bf2(float lo, float hi) {
    uint32_t r;
    asm("cvt.rn.bf16x2.f32 %0, %1, %2;" : "=r"(r) : "f"(hi), "f"(lo));
    return r;
}
__device__ __forceinline__ uint16_t bf16b(float v) {
    return (uint16_t)(f2bf2(v, 0.f) & 0xffffu);
}
__device__ __forceinline__ uint32_t smem_u32(const void* p) {
    uint32_t a;
    asm("{ .reg .u64 t; cvta.to.shared.u64 t, %1; cvt.u32.u64 %0, t; }" : "=r"(a) : "l"(p));
    return a;
}
__device__ __forceinline__ float to_tf32(float x) {
    uint32_t r;
    asm("cvt.rna.tf32.f32 %0, %1;" : "=r"(r) : "f"(x));
    return __uint_as_float(r);
}
__device__ __forceinline__ void mma_tf32(float c[4], uint32_t a0, uint32_t a1,
                                         uint32_t a2, uint32_t a3,
                                         uint32_t b0, uint32_t b1) {
    asm volatile(
        "mma.sync.aligned.m16n8k8.row.col.f32.tf32.tf32.f32 "
        "{%0,%1,%2,%3}, {%4,%5,%6,%7}, {%8,%9}, {%0,%1,%2,%3};"
        : "+f"(c[0]), "+f"(c[1]), "+f"(c[2]), "+f"(c[3])
        : "r"(a0), "r"(a1), "r"(a2), "r"(a3), "r"(b0), "r"(b1));
}
__device__ __forceinline__ void cp16(uint32_t smem_dst, const void* gsrc) {
    asm volatile("cp.async.cg.shared.global [%0], [%1], 16;"
                 :: "r"(smem_dst), "l"(gsrc) : "memory");
}

// ======== prep: fold BN scale into weights, emit smem-image layouts ========
__global__ void prep_kernel(
        const float* __restrict__ w1,
        const float* __restrict__ bg1, const float* __restrict__ bb1,
        const float* __restrict__ bm1, const float* __restrict__ bv1,
        const float* __restrict__ w2,
        const float* __restrict__ bg2, const float* __restrict__ bb2,
        const float* __restrict__ bm2, const float* __restrict__ bv2,
        const float* __restrict__ q_w, const float* __restrict__ q_b,
        const float* __restrict__ k_w, const float* __restrict__ k_b,
        const float* __restrict__ v_w, const float* __restrict__ v_b) {
    const int idx0 = blockIdx.x*256 + threadIdx.x;
    const int STR = gridDim.x*256;
    for (int e = idx0; e < 18432; e += STR) {
        int ch = e / 9216, rem = e % 9216;
        int ci = rem / 288, r2 = rem % 288;
        int co = r2 / 9, tap = r2 % 9;
        float scale = bg1[co] * rsqrtf(bv1[co] + 1e-5f);
        g_w1tf[ch*9472 + ci*296 + co*9 + tap] =
            to_tf32(w1[(co*64 + ch*32 + ci)*9 + tap] * scale);
    }
    for (int e = idx0; e < 18432; e += STR) {
        int co = e / 288, r2 = e % 288;
        int ci = r2 / 9, tap = r2 % 9;
        float scale = bg2[co] * rsqrtf(bv2[co] + 1e-5f);
        g_w2tf[(ci*64 + co)*12 + tap] = to_tf32(w2[e] * scale);
    }
    for (int e = idx0; e < 5120; e += STR) {
        int c = e / 80, o = e % 80;
        float val;
        if (o < 8)       val = q_w[o*64 + c];
        else if (o < 16) val = k_w[(o-8)*64 + c];
        else             val = v_w[(o-16)*64 + c];
        g_wq[c*80 + o] = val;
    }
    if (idx0 < 32)
        g_sh1[idx0] = bb1[idx0] - bm1[idx0]*(bg1[idx0]*rsqrtf(bv1[idx0]+1e-5f));
    if (idx0 < 64)
        g_sh2[idx0] = bb2[idx0] - bm2[idx0]*(bg2[idx0]*rsqrtf(bv2[idx0]+1e-5f));
    if (idx0 < 80)
        g_qb[idx0] = (idx0 < 8) ? q_b[idx0] : (idx0 < 16) ? k_b[idx0-8] : v_b[idx0-16];
}

// ======== conv1: tf32 TC, 8x8 tile, grid 256; weights via cp.async ========
__global__ void __launch_bounds__(256, 2) conv1_kernel(
        const float* __restrict__ xin, float* __restrict__ out) {
    constexpr int WSTR = 296;
    extern __shared__ __align__(16) float sm[];
    float* x_s = sm;                 // 3840 floats
    float* w_s = sm + 3840;          // 9472 floats
    const uint32_t w_su = smem_u32(sm + 3840);

    const int b   = blockIdx.z;
    const int gy0 = blockIdx.y * 8;
    const int gx0 = blockIdx.x * 8;
    const int tid = threadIdx.x;
    const int wid = tid >> 5, lane = tid & 31;
    const int ct = wid & 1, nq = wid >> 1;
    const int lg = lane >> 2, lt = lane & 3;
    const int co0 = ct*16;

    float C[2][4];
#pragma unroll
    for (int i = 0; i < 2; i++)
#pragma unroll
        for (int j = 0; j < 4; j++) C[i][j] = 0.f;

    for (int ch = 0; ch < 2; ch++) {
        // weights: bare cp.async of the prepped smem image
        const float4* wsrc = reinterpret_cast<const float4*>(g_w1tf + ch*9472);
        for (int i = tid; i < 2368; i += 256)
            cp16(w_su + (uint32_t)(i*16), wsrc + i);
        asm volatile("cp.async.commit_group;" ::: "memory");

        const float* xb = xin + (size_t)(b*64 + ch*32)*4096;
        for (int e = tid; e < 3200; e += 256) {
            int ci = e / 100, rem = e % 100;
            int r = rem / 10, c = rem % 10;
            int gy = gy0 - 1 + r, gx = gx0 - 1 + c;
            float val = 0.f;
            if ((unsigned)gy < 64u && (unsigned)gx < 64u)
                val = xb[ci*4096 + gy*64 + gx];
            x_s[(ci*10 + r)*12 + c] = to_tf32(val);
        }
        asm volatile("cp.async.wait_group 0;" ::: "memory");
        __syncthreads();

#pragma unroll
        for (int cc = 0; cc < 4; cc++) {
            const int ci0 = cc*8;
            uint32_t a[9][4];
#pragma unroll
            for (int tap = 0; tap < 9; tap++) {
                a[tap][0] = __float_as_uint(w_s[(ci0 + lt)*WSTR + (co0 + lg)*9 + tap]);
                a[tap][1] = __float_as_uint(w_s[(ci0 + lt)*WSTR + (co0 + 8 + lg)*9 + tap]);
                a[tap][2] = __float_as_uint(w_s[(ci0 + 4 + lt)*WSTR + (co0 + lg)*9 + tap]);
                a[tap][3] = __float_as_uint(w_s[(ci0 + 4 + lt)*WSTR + (co0 + 8 + lg)*9 + tap]);
            }
#pragma unroll
            for (int nt = 0; nt < 2; nt++) {
                const int py = nq*2 + nt;
#pragma unroll
                for (int tap = 0; tap < 9; tap++) {
                    const int dy = tap / 3, dx = tap % 3;
                    const int colb = (py + dy)*12 + dx + lg;
                    uint32_t b0 = __float_as_uint(x_s[(ci0 + lt)*120 + colb]);
                    uint32_t b1 = __float_as_uint(x_s[(ci0 + 4 + lt)*120 + colb]);
                    mma_tf32(C[nt], a[tap][0], a[tap][1], a[tap][2], a[tap][3], b0, b1);
                }
            }
        }
        __syncthreads();
    }

#pragma unroll
    for (int nt = 0; nt < 2; nt++) {
        const int py = nq*2 + nt;
#pragma unroll
        for (int h = 0; h < 2; h++) {
            int co = co0 + h*8 + lg;
            float shift = g_sh1[co];
            float2 v;
            v.x = silu_f(C[nt][2*h]   + shift);
            v.y = silu_f(C[nt][2*h+1] + shift);
            *reinterpret_cast<float2*>(out + (((size_t)(b*32 + co)*64 + gy0 + py)*64 + gx0 + 2*lt)) = v;
        }
    }
}

// ======== conv2 (tf32 TC, 16x8, grid 128) + fused QKV (bf16 out, v^T) ========
__global__ void __launch_bounds__(256) conv2_qkv_kernel(
        const float* __restrict__ xin,
        float* __restrict__ out,
        uint32_t* __restrict__ gqo, uint32_t* __restrict__ gko,
        uint32_t* __restrict__ gvt) {
    constexpr int COUT = 64;
    extern __shared__ __align__(16) float sm[];
    float* x_s = sm;                // [32][10][20] = 6400
    float* w_s = sm + 6400;         // 24576 floats
    // phase-2 overlay:
    float* y_t  = sm;               // [128][65] = 8320
    float* wq_s = sm + 8320;        // [64][80] = 5120
    float* qb_s = sm + 13440;       // [80]
    uint16_t* v_sm = reinterpret_cast<uint16_t*>(sm + 13520);  // [64ch][128px] bf16
    const uint32_t smb = smem_u32(sm);

    const int b   = blockIdx.z;
    const int gy0 = blockIdx.y * 8;
    const int gx0 = blockIdx.x * 16;
    const int tid = threadIdx.x;
    const int wid = tid >> 5, lane = tid & 31;
    const int ct = wid & 3, nh = wid >> 2;
    const int lg = lane >> 2, lt = lane & 3;

    float C[8][4];
#pragma unroll
    for (int i = 0; i < 8; i++)
#pragma unroll
        for (int j = 0; j < 4; j++) C[i][j] = 0.f;

    {
        // weights via cp.async (overlapped with x staging)
        const float4* wsrc = reinterpret_cast<const float4*>(g_w2tf);
        for (int i = tid; i < 6144; i += 256)
            cp16(smb + 25600u + (uint32_t)(i*16), wsrc + i);
        asm volatile("cp.async.commit_group;" ::: "memory");

        const float* xb = xin + (size_t)(b*32)*4096;
        for (int e = tid; e < 32*10*18; e += 256) {
            int ci = e / 180; int rem = e % 180;
            int r = rem / 18, c = rem % 18;
            int gy = gy0 - 1 + r, gx = gx0 - 1 + c;
            float val = 0.f;
            if ((unsigned)gy < 64u && (unsigned)gx < 64u)
                val = xb[ci*4096 + gy*64 + gx];
            x_s[(ci*10 + r)*20 + c] = to_tf32(val);
        }
        asm volatile("cp.async.wait_group 0;" ::: "memory");
        __syncthreads();

#pragma unroll
        for (int cc = 0; cc < 4; cc++) {
            const int ci0 = cc*8;
            uint32_t a[9][4];
            const int co0 = ct*16;
#pragma unroll
            for (int tap = 0; tap < 9; tap++) {
                a[tap][0] = __float_as_uint(w_s[((ci0 + lt)*64 + co0 + lg)*12 + tap]);
                a[tap][1] = __float_as_uint(w_s[((ci0 + lt)*64 + co0 + 8 + lg)*12 + tap]);
                a[tap][2] = __float_as_uint(w_s[((ci0 + 4 + lt)*64 + co0 + lg)*12 + tap]);
                a[tap][3] = __float_as_uint(w_s[((ci0 + 4 + lt)*64 + co0 + 8 + lg)*12 + tap]);
            }
#pragma unroll
            for (int nt = 0; nt < 8; nt++) {
                const int n0 = (nh*8 + nt)*8;
                const int py = n0 >> 4, px0 = n0 & 15;
#pragma unroll
                for (int tap = 0; tap < 9; tap++) {
                    const int dy = tap / 3, dx = tap % 3;
                    const int colb = (py + dy)*20 + px0 + dx + lg;
                    uint32_t b0 = __float_as_uint(x_s[(ci0 + lt)*200 + colb]);
                    uint32_t b1 = __float_as_uint(x_s[(ci0 + 4 + lt)*200 + colb]);
                    mma_tf32(C[nt], a[tap][0], a[tap][1], a[tap][2], a[tap][3], b0, b1);
                }
            }
        }
        __syncthreads();   // conv smem reads done; overlay safe
    }

    // issue qkv weight/bias cp.asyncs (land while epilogue runs)
    {
        const float4* wqsrc = reinterpret_cast<const float4*>(g_wq);
        for (int i = tid; i < 1280; i += 256)
            cp16(smb + 33280u + (uint32_t)(i*16), wqsrc + i);
        if (tid < 20)
            cp16(smb + 53760u + (uint32_t)(tid*16),
                 reinterpret_cast<const float4*>(g_qb) + tid);
        asm volatile("cp.async.commit_group;" ::: "memory");
    }

    // epilogue: SiLU(C + shift) -> gmem y AND smem y_t[px][co]
#pragma unroll
    for (int nt = 0; nt < 8; nt++) {
        const int n0 = (nh*8 + nt)*8;
        const int py = n0 >> 4;
        const int px = (n0 & 15) + 2*lt;
#pragma unroll
        for (int h = 0; h < 2; h++) {
            int co = ct*16 + h*8 + lg;
            float shift = g_sh2[co];
            float v0 = silu_f(C[nt][2*h]   + shift);
            float v1 = silu_f(C[nt][2*h+1] + shift);
            *reinterpret_cast<float2*>(out + (((size_t)(b*COUT + co)*64 + gy0 + py)*64 + gx0 + px)) =
                make_float2(v0, v1);
            y_t[(py*16 + px)*65 + co]     = v0;
            y_t[(py*16 + px + 1)*65 + co] = v1;
        }
    }
    asm volatile("cp.async.wait_group 0;" ::: "memory");
    __syncthreads();

    // qkv: 2 threads per pixel, 40 outputs each
    const int px   = tid >> 1;
    const int half = tid & 1;
    float a2[40];
    const float* bb2 = qb_s + half*40;
#pragma unroll
    for (int j = 0; j < 40; j++) a2[j] = bb2[j];
    for (int c = 0; c < 64; c++) {
        float yv = y_t[px*65 + c];
        const float4* wp = reinterpret_cast<const float4*>(wq_s + c*80 + half*40);
#pragma unroll
        for (int j4 = 0; j4 < 10; j4++) {
            float4 w4 = wp[j4];
            a2[j4*4+0] = fmaf(w4.x, yv, a2[j4*4+0]);
            a2[j4*4+1] = fmaf(w4.y, yv, a2[j4*4+1]);
            a2[j4*4+2] = fmaf(w4.z, yv, a2[j4*4+2]);
            a2[j4*4+3] = fmaf(w4.w, yv, a2[j4*4+3]);
        }
    }
    const int n = (gy0 + (px >> 4))*64 + gx0 + (px & 15);
    const size_t row = (size_t)(b*4096 + n);
    if (half == 0) {
        *reinterpret_cast<uint4*>(gqo + row*4) = make_uint4(
            f2bf2(a2[0], a2[1]), f2bf2(a2[2], a2[3]),
            f2bf2(a2[4], a2[5]), f2bf2(a2[6], a2[7]));
        *reinterpret_cast<uint4*>(gko + row*4) = make_uint4(
            f2bf2(a2[8],  a2[9]),  f2bf2(a2[10], a2[11]),
            f2bf2(a2[12], a2[13]), f2bf2(a2[14], a2[15]));
#pragma unroll
        for (int j = 0; j < 24; j++)
            v_sm[j*128 + px] = bf16b(a2[16 + j]);
    } else {
#pragma unroll
        for (int j = 0; j < 40; j++)
            v_sm[(24 + j)*128 + px] = bf16b(a2[j]);
    }
    __syncthreads();

    // coalesced v^T write: g_vt[b][ch][n/2]
    const uint32_t* v32 = reinterpret_cast<const uint32_t*>(v_sm);
    for (int i = tid; i < 4096; i += 256) {
        int chn = i >> 6, lp = i & 63;
        int np = (gy0 + (lp >> 3))*32 + (gx0 >> 1) + (lp & 7);
        gvt[((size_t)(b*64 + chn))*2048 + np] = v32[chn*64 + lp];
    }
}

// ---------------- flash attention: R14 exact (bf16, cp.async 3-deep) ----------------
__global__ void __launch_bounds__(256, 1) flash_hmma_kernel(
        const uint32_t* __restrict__ gq,
        const uint32_t* __restrict__ gk,
        const uint32_t* __restrict__ gvt,
        const float* __restrict__ x,
        const float* __restrict__ gy,
        const float* __restrict__ gamma,
        float* __restrict__ outp) {
    extern __shared__ __align__(128) unsigned char smem_all[];
    const uint32_t smb = smem_u32(smem_all);
    float* t_s = reinterpret_cast<float*>(smem_all);   // epilogue overlay [128][66]

    const int b    = blockIdx.y;
    const int qt   = blockIdx.x;
    const int tid  = threadIdx.x;
    const int wid  = tid >> 5;
    const int lane = tid & 31;
    const int g    = lane >> 2;
    const int t    = lane & 3;

    const int qrow = b*4096 + qt*128 + wid*16 + g;
    const uint32_t qa0 = gq[(size_t)qrow*4 + t];
    const uint32_t qa1 = gq[(size_t)(qrow+8)*4 + t];

    float o[8][4];
#pragma unroll
    for (int i = 0; i < 8; i++)
#pragma unroll
        for (int j = 0; j < 4; j++) o[i][j] = 0.f;
    float rs0 = 0.f, rs1 = 0.f;

    const uint32_t* kb = gk + (size_t)b*4096*4;
    const uint32_t* vtb = gvt + (size_t)b*64*2048;

    const int sel  = lane >> 3;
    const int l8   = lane & 7;
    const int ch_off    = ((sel >> 1) << 3) + l8;
    const int chunk_off = sel & 1;

    auto issue_tile = [&](int kt, int buf) {
        if (tid < 128)
            cp16(smb + (uint32_t)(buf*2048) + tid*16,
                 kb + (size_t)(kt*128 + tid)*4);
        uint32_t vbase = smb + 6144u + (uint32_t)buf*17408u;
#pragma unroll
        for (int it = 0; it < 4; it++) {
            int c = it*256 + tid;
            int ch = c >> 4, chunk = c & 15;
            cp16(vbase + (uint32_t)(ch*272 + (((chunk ^ (ch>>3)) & 15) << 4)),
                 vtb + (size_t)ch*2048 + kt*64 + chunk*4);
        }
        asm volatile("cp.async.commit_group;" ::: "memory");
    };

    issue_tile(0, 0);
    issue_tile(1, 1);

    for (int kt = 0; kt < 32; kt++) {
        const int cur = kt % 3;
        if (kt < 31) {
            asm volatile("cp.async.wait_group 1;" ::: "memory");
        } else {
            asm volatile("cp.async.wait_group 0;" ::: "memory");
        }
        __syncthreads();
        if (kt + 2 < 32)
            issue_tile(kt + 2, (kt + 2) % 3);

        const unsigned char* Kc = smem_all + cur*2048;
        const uint32_t vbase = smb + 6144u + (uint32_t)cur*17408u;

        float e[16][4];
#pragma unroll
        for (int nt = 0; nt < 16; nt++) {
            uint32_t kb32 = *reinterpret_cast<const uint32_t*>(Kc + nt*128 + lane*4);
            float d0 = 0.f, d1 = 0.f, d2 = 0.f, d3 = 0.f;
            asm volatile(
                "mma.sync.aligned.m16n8k8.row.col.f32.bf16.bf16.f32 "
                "{%0,%1,%2,%3}, {%4,%5}, {%6}, {%0,%1,%2,%3};"
                : "+f"(d0), "+f"(d1), "+f"(d2), "+f"(d3)
                : "r"(qa0), "r"(qa1), "r"(kb32));
            e[nt][0] = d0; e[nt][1] = d1; e[nt][2] = d2; e[nt][3] = d3;
        }
#pragma unroll
        for (int nt = 0; nt < 16; nt++) {
            e[nt][0] = __expf(e[nt][0]);
            e[nt][1] = __expf(e[nt][1]);
            e[nt][2] = __expf(e[nt][2]);
            e[nt][3] = __expf(e[nt][3]);
            rs0 += e[nt][0] + e[nt][1];
            rs1 += e[nt][2] + e[nt][3];
        }

#pragma unroll
        for (int ks = 0; ks < 8; ks++) {
            uint32_t a0 = f2bf2(e[2*ks][0],   e[2*ks][1]);
            uint32_t a1 = f2bf2(e[2*ks][2],   e[2*ks][3]);
            uint32_t a2 = f2bf2(e[2*ks+1][0], e[2*ks+1][1]);
            uint32_t a3 = f2bf2(e[2*ks+1][2], e[2*ks+1][3]);
            int chunk = 2*ks + chunk_off;
#pragma unroll
            for (int nt2 = 0; nt2 < 4; nt2++) {
                int ch = nt2*16 + ch_off;
                uint32_t addr = vbase + (uint32_t)(ch*272 + (((chunk ^ (ch>>3)) & 15) << 4));
                uint32_t b0, b1, b2, b3;
                asm volatile(
                    "ldmatrix.sync.aligned.m8n8.x4.shared.b16 {%0,%1,%2,%3}, [%4];"
                    : "=r"(b0), "=r"(b1), "=r"(b2), "=r"(b3) : "r"(addr));
                asm volatile(
                    "mma.sync.aligned.m16n8k16.row.col.f32.bf16.bf16.f32 "
                    "{%0,%1,%2,%3}, {%4,%5,%6,%7}, {%8,%9}, {%0,%1,%2,%3};"
                    : "+f"(o[nt2*2][0]), "+f"(o[nt2*2][1]), "+f"(o[nt2*2][2]), "+f"(o[nt2*2][3])
                    : "r"(a0), "r"(a1), "r"(a2), "r"(a3), "r"(b0), "r"(b1));
                asm volatile(
                    "mma.sync.aligned.m16n8k16.row.col.f32.bf16.bf16.f32 "
                    "{%0,%1,%2,%3}, {%4,%5,%6,%7}, {%8,%9}, {%0,%1,%2,%3};"
                    : "+f"(o[nt2*2+1][0]), "+f"(o[nt2*2+1][1]), "+f"(o[nt2*2+1][2]), "+f"(o[nt2*2+1][3])
                    : "r"(a0), "r"(a1), "r"(a2), "r"(a3), "r"(b2), "r"(b3));
            }
        }
        __syncthreads();
    }

    rs0 += __shfl_xor_sync(0xffffffffu, rs0, 1);
    rs0 += __shfl_xor_sync(0xffffffffu, rs0, 2);
    rs1 += __shfl_xor_sync(0xffffffffu, rs1, 1);
    rs1 += __shfl_xor_sync(0xffffffffu, rs1, 2);
    const float inv0 = 1.0f / rs0, inv1 = 1.0f / rs1;

    const int r0 = wid*16 + g;
#pragma unroll
    for (int nt = 0; nt < 8; nt++) {
        int ch = nt*8 + 2*t;
        *reinterpret_cast<float2*>(t_s + r0*66 + ch) =
            make_float2(o[nt][0]*inv0, o[nt][1]*inv0);
        *reinterpret_cast<float2*>(t_s + (r0+8)*66 + ch) =
            make_float2(o[nt][2]*inv1, o[nt][3]*inv1);
    }
    __syncthreads();

    const float g2 = 2.0f * gamma[0];
    const int c  = tid >> 2;
    const int i0 = (tid & 3) * 32;
    const size_t base = ((size_t)(b*64 + c))*4096 + qt*128 + i0;
#pragma unroll
    for (int i4 = 0; i4 < 8; i4++) {
        float4 xv = *reinterpret_cast<const float4*>(x  + base + i4*4);
        float4 yv = *reinterpret_cast<const float4*>(gy + base + i4*4);
        float4 ov;
        ov.x = xv.x + 2.f*yv.x + g2*t_s[(i0 + i4*4 + 0)*66 + c];
        ov.y = xv.y + 2.f*yv.y + g2*t_s[(i0 + i4*4 + 1)*66 + c];
        ov.z = xv.z + 2.f*yv.z + g2*t_s[(i0 + i4*4 + 2)*66 + c];
        ov.w = xv.w + 2.f*yv.w + g2*t_s[(i0 + i4*4 + 3)*66 + c];
        *reinterpret_cast<float4*>(outp + base + i4*4) = ov;
    }
}

// ---------------- launch ----------------
extern "C" void kernel_launch(void* const* d_in, const int* in_sizes, int n_in,
                              void* d_out, int out_size) {
    const float* x     = (const float*)d_in[0];
    const float* cv1_w = (const float*)d_in[1];
    const float* bn1_g = (const float*)d_in[2];
    const float* bn1_b = (const float*)d_in[3];
    const float* bn1_m = (const float*)d_in[4];
    const float* bn1_v = (const float*)d_in[5];
    const float* cv2_w = (const float*)d_in[6];
    const float* bn2_g = (const float*)d_in[7];
    const float* bn2_b = (const float*)d_in[8];
    const float* bn2_m = (const float*)d_in[9];
    const float* bn2_v = (const float*)d_in[10];
    const float* q_w   = (const float*)d_in[11];
    const float* q_b   = (const float*)d_in[12];
    const float* k_w   = (const float*)d_in[13];
    const float* k_b   = (const float*)d_in[14];
    const float* v_w   = (const float*)d_in[15];
    const float* v_b   = (const float*)d_in[16];
    const float* gamma = (const float*)d_in[17];
    float* out = (float*)d_out;

    void *py1, *py, *pq, *pk, *pvt;
    cudaGetSymbolAddress(&py1, g_y1);
    cudaGetSymbolAddress(&py,  g_y);
    cudaGetSymbolAddress(&pq,  g_q);
    cudaGetSymbolAddress(&pk,  g_k);
    cudaGetSymbolAddress(&pvt, g_vt);

    const int SMEM_C1 = (3840 + 9472) * 4;    // 53248
    const int SMEM_C2 = (6400 + 24576) * 4;   // 123904
    const int SMEM_FL = 3*2048 + 3*17408;     // 58368

    cudaFuncSetAttribute(conv1_kernel, cudaFuncAttributeMaxDynamicSharedMemorySize, SMEM_C1);
    cudaFuncSetAttribute(conv2_qkv_kernel, cudaFuncAttributeMaxDynamicSharedMemorySize, SMEM_C2);
    cudaFuncSetAttribute(flash_hmma_kernel, cudaFuncAttributeMaxDynamicSharedMemorySize, SMEM_FL);

    prep_kernel<<<42, 256>>>(cv1_w, bn1_g, bn1_b, bn1_m, bn1_v,
                             cv2_w, bn2_g, bn2_b, bn2_m, bn2_v,
                             q_w, q_b, k_w, k_b, v_w, v_b);
    conv1_kernel<<<dim3(8,8,4), 256, SMEM_C1>>>(x, (float*)py1);
    conv2_qkv_kernel<<<dim3(4,8,4), 256, SMEM_C2>>>(
        (const float*)py1, (float*)py,
        (uint32_t*)pq, (uint32_t*)pk, (uint32_t*)pvt);
    flash_hmma_kernel<<<dim3(32,4), 256, SMEM_FL>>>(
        (const uint32_t*)pq, (const uint32_t*)pk, (const uint32_t*)pvt,
        x, (const float*)py, gamma, out);
}